// round 14
// baseline (speedup 1.0000x reference)
#include <cuda_runtime.h>
#include <cuda_fp16.h>
#include <math_constants.h>
#include <cstdint>

// Problem constants
#define D_MODEL   2048
#define N_HEADS   16
#define N_KV      4
#define DH        128
#define B_        2
#define T_        2048
#define QKV_DIM   3072          // 2048 + 2*4*128
#define ROWS      (B_*T_)       // 4096

// Scratch (static device allocations only)
__device__ __half  g_qkvh[ROWS * QKV_DIM];      // 24 MB
__device__ __half  g_yh  [ROWS * D_MODEL];      // 16 MB
__device__ __half  g_xh  [ROWS * D_MODEL];      // 16 MB  (fp16 x)
__device__ __half  g_wqT [QKV_DIM * D_MODEL];   // 12 MB  (fp16 Wqkv^T  [N][K])
__device__ __half  g_woT [D_MODEL * D_MODEL];   //  8 MB  (fp16 Wo^T    [N][K])
__device__ float2  g_rtab[T_ * 64];             //  1 MB  (cos/sin table)

// ---------------------------------------------------------------------------
// helpers
// ---------------------------------------------------------------------------
__device__ __forceinline__ void mma16(float c[4], const unsigned a[4],
                                      unsigned b0, unsigned b1) {
    asm volatile(
        "mma.sync.aligned.m16n8k16.row.col.f32.f16.f16.f32 "
        "{%0,%1,%2,%3},{%4,%5,%6,%7},{%8,%9},{%0,%1,%2,%3};"
        : "+f"(c[0]), "+f"(c[1]), "+f"(c[2]), "+f"(c[3])
        : "r"(a[0]), "r"(a[1]), "r"(a[2]), "r"(a[3]), "r"(b0), "r"(b1));
}

#define LDM4(d, addr) \
    asm volatile("ldmatrix.sync.aligned.m8n8.x4.shared.b16 {%0,%1,%2,%3}, [%4];" \
        : "=r"((d)[0]), "=r"((d)[1]), "=r"((d)[2]), "=r"((d)[3]) : "r"(addr))
#define LDM4T(d, addr) \
    asm volatile("ldmatrix.sync.aligned.m8n8.x4.trans.shared.b16 {%0,%1,%2,%3}, [%4];" \
        : "=r"((d)[0]), "=r"((d)[1]), "=r"((d)[2]), "=r"((d)[3]) : "r"(addr))

#define CPA16(dst_u32, src_ptr) \
    asm volatile("cp.async.cg.shared.global [%0], [%1], 16;" :: "r"(dst_u32), "l"(src_ptr))
#define CPA_COMMIT() asm volatile("cp.async.commit_group;")
#define CPA_WAIT(n)  asm volatile("cp.async.wait_group %0;" :: "n"(n))

__device__ __forceinline__ unsigned h2u(__half2 h) { return *(unsigned*)&h; }
__device__ __forceinline__ float ex2f(float x) {
    float r;
    asm("ex2.approx.ftz.f32 %0, %1;" : "=f"(r) : "f"(x));
    return r;
}

// ---------------------------------------------------------------------------
// pre-pass: fp32 -> fp16 conversion of x
// ---------------------------------------------------------------------------
__global__ __launch_bounds__(256) void conv_h_kernel(const float* __restrict__ in,
                                                     __half2* __restrict__ out, int n4) {
    int i = blockIdx.x * 256 + threadIdx.x;
    if (i >= n4) return;
    float4 v = ((const float4*)in)[i];
    out[2 * i]     = __floats2half2_rn(v.x, v.y);
    out[2 * i + 1] = __floats2half2_rn(v.z, v.w);
}

// ---------------------------------------------------------------------------
// pre-pass: transpose + convert weights: W[K][N] fp32 -> WT[N][K] fp16
// ---------------------------------------------------------------------------
__global__ __launch_bounds__(256) void transpose_h_kernel(const float* __restrict__ in,
                                                          __half* __restrict__ out,
                                                          int K, int N) {
    __shared__ float tile[64][33];
    const int tx = threadIdx.x, ty = threadIdx.y;   // 32 x 8
    const int n0 = blockIdx.x * 32, k0 = blockIdx.y * 64;
#pragma unroll
    for (int jj = 0; jj < 8; jj++)
        tile[ty + 8 * jj][tx] = in[(size_t)(k0 + ty + 8 * jj) * N + n0 + tx];
    __syncthreads();
#pragma unroll
    for (int it = 0; it < 4; it++) {
        const int r = ty + 8 * it;                  // out row within n-tile
        __half2 h = __floats2half2_rn(tile[2 * tx][r], tile[2 * tx + 1][r]);
        *(__half2*)&out[(size_t)(n0 + r) * K + k0 + 2 * tx] = h;
    }
}

// ---------------------------------------------------------------------------
// rope table: cos/sin for (t, i)
// ---------------------------------------------------------------------------
__global__ __launch_bounds__(256) void rope_table_kernel(const int* __restrict__ start_pos) {
    int id = blockIdx.x * 256 + threadIdx.x;    // < 2048*64
    int t = id >> 6, i = id & 63;
    float pos = (float)(start_pos[0] + t);
    float inv = exp2f(-(float)i * (13.287712379549449f / 64.0f));
    float ang = pos * inv;
    float s, c;
    sincosf(ang, &s, &c);
    g_rtab[id] = make_float2(c, s);
}

// ---------------------------------------------------------------------------
// fp16 GEMM: C[M,N] = A[M,K] @ BT[N][K]^T; fp32 accum.
// 128x128 CTA tile, 128 threads (4 warps, 64x64 warp tile), BK=64,
// 128B swizzled smem rows, cp.async THREE-stage pipeline, ldmatrix frags.
// ROPE: rotary embedding fused into epilogue for columns < 2560 (q,k regions).
// ---------------------------------------------------------------------------
#define G3STAGE 32768                    // bytes per stage (A 16K + B 16K)
#define GEMM_SMEM (3 * G3STAGE)          // 98304 bytes

template <bool HALF_OUT, bool ROPE>
__global__ __launch_bounds__(128) void gemm_h(const __half* __restrict__ A,
                                              const __half* __restrict__ Bt,
                                              void* __restrict__ Cv,
                                              int M, int N, int K) {
    extern __shared__ char smraw[];
    const unsigned sb = (unsigned)__cvta_generic_to_shared(smraw);

    const int tid = threadIdx.x;
    const int wid = tid >> 5, lane = tid & 31;
    const int g = lane >> 2, t = lane & 3;
    const int j = lane & 7, s1 = (lane >> 3) & 1, s2 = (lane >> 4) & 1;
    const int warp_m = (wid >> 1) * 64;
    const int warp_n = (wid & 1) * 64;
    const int bx = blockIdx.x, by = blockIdx.y;

    const unsigned a_base = (unsigned)((warp_m + s1 * 8 + j) * 128);
    const unsigned b_base = 16384u + (unsigned)((warp_n + s2 * 8 + j) * 128);
    const unsigned cxa = (unsigned)(s2 ^ j);
    const unsigned cxb = (unsigned)(s1 ^ j);

    const int lr = tid >> 3;             // 0..15
    const int c8 = tid & 7;              // 16B chunk in 128B row
    const unsigned lcx = (unsigned)(c8 ^ (lr & 7)) << 4;

    const int nst = K / 64;

    float acc[4][8][4];
#pragma unroll
    for (int i = 0; i < 4; i++)
#pragma unroll
        for (int jj = 0; jj < 8; jj++)
#pragma unroll
            for (int k = 0; k < 4; k++) acc[i][jj][k] = 0.f;

#define GLOAD(kt_) do {                                                          \
        const unsigned _tb = sb + ((kt_) % 3) * G3STAGE;                         \
        const int _ko = (kt_) * 64;                                              \
        _Pragma("unroll")                                                        \
        for (int p = 0; p < 8; p++) {                                            \
            const int r = lr + p * 16;                                           \
            CPA16(_tb + r * 128 + lcx, A + (size_t)(by * 128 + r) * K + _ko + c8 * 8); \
        }                                                                        \
        _Pragma("unroll")                                                        \
        for (int p = 0; p < 8; p++) {                                            \
            const int r = lr + p * 16;                                           \
            CPA16(_tb + 16384 + r * 128 + lcx, Bt + (size_t)(bx * 128 + r) * K + _ko + c8 * 8); \
        }                                                                        \
        CPA_COMMIT();                                                            \
    } while (0)

    GLOAD(0);
    GLOAD(1);

    for (int kt = 0; kt < nst; kt++) {
        CPA_WAIT(1);
        __syncthreads();
        if (kt + 2 < nst) GLOAD(kt + 2);

        const unsigned stg = sb + (kt % 3) * G3STAGE;
#pragma unroll
        for (int kk = 0; kk < 4; kk++) {
            unsigned af[4][4], bf[4][4];
#pragma unroll
            for (int mt = 0; mt < 4; mt++)
                LDM4(af[mt], stg + a_base + mt * 2048 + (((2u * kk) ^ cxa) << 4));
#pragma unroll
            for (int np = 0; np < 4; np++)
                LDM4(bf[np], stg + b_base + np * 2048 + (((2u * kk) ^ cxb) << 4));
#pragma unroll
            for (int mt = 0; mt < 4; mt++)
#pragma unroll
                for (int np = 0; np < 4; np++) {
                    mma16(acc[mt][np * 2],     af[mt], bf[np][0], bf[np][1]);
                    mma16(acc[mt][np * 2 + 1], af[mt], bf[np][2], bf[np][3]);
                }
        }
    }
#undef GLOAD

#pragma unroll
    for (int mt = 0; mt < 4; mt++) {
#pragma unroll
        for (int nt = 0; nt < 8; nt++) {
            const int r0 = by * 128 + warp_m + mt * 16 + g;
            const int c0 = bx * 128 + warp_n + nt * 8 + 2 * t;
            float v0 = acc[mt][nt][0], v1 = acc[mt][nt][1];
            float v2 = acc[mt][nt][2], v3 = acc[mt][nt][3];
            if (ROPE && c0 < 2560) {
                const int i = (c0 & 127) >> 1;
                float2 csA = g_rtab[(r0 & (T_ - 1)) * 64 + i];
                float2 csB = g_rtab[((r0 + 8) & (T_ - 1)) * 64 + i];
                float e0 = v0 * csA.x - v1 * csA.y;
                float o0 = v0 * csA.y + v1 * csA.x;
                float e1 = v2 * csB.x - v3 * csB.y;
                float o1 = v2 * csB.y + v3 * csB.x;
                v0 = e0; v1 = o0; v2 = e1; v3 = o1;
            }
            if (HALF_OUT) {
                __half* C = (__half*)Cv;
                *(__half2*)&C[(size_t)r0 * N + c0]       = __floats2half2_rn(v0, v1);
                *(__half2*)&C[(size_t)(r0 + 8) * N + c0] = __floats2half2_rn(v2, v3);
            } else {
                float* C = (float*)Cv;
                *(float2*)&C[(size_t)r0 * N + c0]       = make_float2(v0, v1);
                *(float2*)&C[(size_t)(r0 + 8) * N + c0] = make_float2(v2, v3);
            }
        }
    }
}

// ---------------------------------------------------------------------------
// Flash attention (causal, GQA), fp16 mma + ldmatrix, cp.async dbuf.
// 128 threads / 4 warps; q-tile 64; kv-tile 64. Q staged through K-stage-1
// smem then hoisted to registers -> NO dedicated Q region.
// smem bytes: Ks 2x[64][272B] @0 | Vs 2x[64][256B sw] @34816  => 67584 total
// 3 CTAs/SM (202 KB smem, regs capped by launch_bounds(128,3)).
// ---------------------------------------------------------------------------
#define FK_OFF 0u
#define FV_OFF 34816u
#define FLASH_SMEM 67584

__global__ __launch_bounds__(128, 3) void flash_h(const __half* __restrict__ qkv,
                                                  __half* __restrict__ y) {
    extern __shared__ char smraw[];
    const unsigned sb = (unsigned)__cvta_generic_to_shared(smraw);

    const int tid = threadIdx.x;
    const int wid = tid >> 5, lane = tid & 31;
    const int g = lane >> 2, t = lane & 3;
    const int j = lane & 7, s1 = (lane >> 3) & 1, s2 = (lane >> 4) & 1;
    const int qb = gridDim.x - 1 - blockIdx.x;   // long blocks first
    const int h = blockIdx.y, b = blockIdx.z;
    const int kvh = h >> 2;
    const int q0 = wid * 16;
    const float SC = 0.08838834764831845f * 1.4426950408889634f;  // scale*log2(e)

    // Q staged in K-stage-1 region (offset 17408), 272B pitch
    const unsigned q_lane = 17408u + (unsigned)((q0 + s1 * 8 + j) * 272 + s2 * 16);
    const unsigned k_lane = FK_OFF + (unsigned)((s2 * 8 + j) * 272 + s1 * 16);
    const unsigned vrow   = (unsigned)((s1 * 8 + j) * 256);

    const int lrow8 = tid >> 4;          // 0..7
    const int lc = tid & 15;             // 16B chunk within row

    // Q tile -> K-stage-1 smem (group A)
#pragma unroll
    for (int it = 0; it < 8; it++) {
        const int row = it * 8 + lrow8;
        CPA16(sb + 17408u + row * 272 + lc * 16,
              qkv + (size_t)(b * T_ + qb * 64 + row) * QKV_DIM + h * DH + lc * 8);
    }
    CPA_COMMIT();

    const int ntiles = qb + 1;

#define KV_LOAD(kt_) do {                                                        \
        const unsigned _stg = (unsigned)((kt_) & 1);                             \
        _Pragma("unroll")                                                        \
        for (int it = 0; it < 8; it++) {                                         \
            const int row = it * 8 + lrow8;                                      \
            const __half* gp = qkv + (size_t)(b * T_ + (kt_) * 64 + row) * QKV_DIM \
                               + D_MODEL + kvh * DH + lc * 8;                    \
            CPA16(sb + FK_OFF + _stg * 17408 + row * 272 + lc * 16, gp);         \
            CPA16(sb + FV_OFF + _stg * 16384 + row * 256 + ((lc ^ (row & 7)) << 4), gp + N_KV * DH); \
        }                                                                        \
        CPA_COMMIT();                                                            \
    } while (0)

    // KV stage 0 (group B) — goes to K/V stage 0, not the Q region
    KV_LOAD(0);

    // hoist Q fragments to registers (wait group A done; B may be in flight)
    unsigned qf[8][4];
    CPA_WAIT(1);
    __syncthreads();
#pragma unroll
    for (int kk = 0; kk < 8; kk++)
        LDM4(qf[kk], sb + q_lane + kk * 32);
    __syncthreads();   // all warps hoisted before KV_LOAD(1) overwrites stage 1

    float m_lo = -1e30f, m_hi = -1e30f, l_lo = 0.f, l_hi = 0.f;
    float o[16][4];
#pragma unroll
    for (int i = 0; i < 16; i++)
#pragma unroll
        for (int jj = 0; jj < 4; jj++) o[i][jj] = 0.f;

#define FLASH_TILE(kt_, MASKED) do {                                              \
    if ((kt_) + 1 < ntiles) { KV_LOAD((kt_) + 1); CPA_WAIT(1); }                  \
    else                    { CPA_WAIT(0); }                                      \
    __syncthreads();                                                              \
    const unsigned kstg = ((kt_) & 1) * 17408;                                    \
    const unsigned vstg = FV_OFF + ((kt_) & 1) * 16384;                           \
    float s[8][4];                                                                \
    _Pragma("unroll")                                                             \
    for (int nt = 0; nt < 8; nt++) { s[nt][0]=0.f; s[nt][1]=0.f; s[nt][2]=0.f; s[nt][3]=0.f; } \
    _Pragma("unroll")                                                             \
    for (int kk = 0; kk < 8; kk++) {                                              \
        _Pragma("unroll")                                                         \
        for (int np = 0; np < 4; np++) {                                          \
            unsigned kb[4];                                                       \
            LDM4(kb, sb + k_lane + kstg + np * 4352 + kk * 32);                   \
            mma16(s[np * 2],     qf[kk], kb[0], kb[1]);                           \
            mma16(s[np * 2 + 1], qf[kk], kb[2], kb[3]);                           \
        }                                                                         \
    }                                                                             \
    float ml = -1e30f, mh = -1e30f;                                               \
    if (MASKED) {                                                                 \
        const int rlo = qb * 64 + q0 + g;                                         \
        const int rhi = rlo + 8;                                                  \
        const int cb = (kt_) * 64;                                                \
        _Pragma("unroll")                                                         \
        for (int nt = 0; nt < 8; nt++) {                                          \
            const int c0 = cb + nt * 8 + 2 * t, c1 = c0 + 1;                      \
            if (c0 > rlo) s[nt][0] = -1e30f;                                      \
            if (c1 > rlo) s[nt][1] = -1e30f;                                      \
            if (c0 > rhi) s[nt][2] = -1e30f;                                      \
            if (c1 > rhi) s[nt][3] = -1e30f;                                      \
        }                                                                         \
    }                                                                             \
    _Pragma("unroll")                                                             \
    for (int nt = 0; nt < 8; nt++) {                                              \
        ml = fmaxf(ml, fmaxf(s[nt][0], s[nt][1]));                                \
        mh = fmaxf(mh, fmaxf(s[nt][2], s[nt][3]));                                \
    }                                                                             \
    ml = fmaxf(ml, __shfl_xor_sync(0xffffffffu, ml, 1));                          \
    ml = fmaxf(ml, __shfl_xor_sync(0xffffffffu, ml, 2));                          \
    mh = fmaxf(mh, __shfl_xor_sync(0xffffffffu, mh, 1));                          \
    mh = fmaxf(mh, __shfl_xor_sync(0xffffffffu, mh, 2));                          \
    const float mnl = fmaxf(m_lo, ml);                                            \
    const float mnh = fmaxf(m_hi, mh);                                            \
    const float nbl = -mnl * SC;                                                  \
    const float nbh = -mnh * SC;                                                  \
    float ll = 0.f, lh = 0.f;                                                     \
    _Pragma("unroll")                                                             \
    for (int nt = 0; nt < 8; nt++) {                                              \
        s[nt][0] = ex2f(fmaf(s[nt][0], SC, nbl));                                 \
        s[nt][1] = ex2f(fmaf(s[nt][1], SC, nbl));                                 \
        s[nt][2] = ex2f(fmaf(s[nt][2], SC, nbh));                                 \
        s[nt][3] = ex2f(fmaf(s[nt][3], SC, nbh));                                 \
        ll += s[nt][0] + s[nt][1];                                                \
        lh += s[nt][2] + s[nt][3];                                                \
    }                                                                             \
    ll += __shfl_xor_sync(0xffffffffu, ll, 1);                                    \
    ll += __shfl_xor_sync(0xffffffffu, ll, 2);                                    \
    lh += __shfl_xor_sync(0xffffffffu, lh, 1);                                    \
    lh += __shfl_xor_sync(0xffffffffu, lh, 2);                                    \
    if (__all_sync(0xffffffffu, (mnl == m_lo) & (mnh == m_hi))) {                 \
        l_lo += ll; l_hi += lh;                                                   \
    } else {                                                                      \
        const float al = ex2f((m_lo - mnl) * SC);                                 \
        const float ah = ex2f((m_hi - mnh) * SC);                                 \
        l_lo = l_lo * al + ll;                                                    \
        l_hi = l_hi * ah + lh;                                                    \
        _Pragma("unroll")                                                         \
        for (int nt = 0; nt < 16; nt++) {                                         \
            o[nt][0] *= al; o[nt][1] *= al;                                       \
            o[nt][2] *= ah; o[nt][3] *= ah;                                       \
        }                                                                         \
    }                                                                             \
    m_lo = mnl; m_hi = mnh;                                                       \
    _Pragma("unroll")                                                             \
    for (int kk = 0; kk < 4; kk++) {                                              \
        unsigned a[4];                                                            \
        a[0] = h2u(__floats2half2_rn(s[2 * kk][0],     s[2 * kk][1]));            \
        a[1] = h2u(__floats2half2_rn(s[2 * kk][2],     s[2 * kk][3]));            \
        a[2] = h2u(__floats2half2_rn(s[2 * kk + 1][0], s[2 * kk + 1][1]));        \
        a[3] = h2u(__floats2half2_rn(s[2 * kk + 1][2], s[2 * kk + 1][3]));        \
        _Pragma("unroll")                                                         \
        for (int np = 0; np < 8; np++) {                                          \
            unsigned vb[4];                                                       \
            const unsigned chunk = (unsigned)(((np << 1) | s2) ^ j);              \
            LDM4T(vb, sb + vstg + kk * 4096 + vrow + (chunk << 4));               \
            mma16(o[np * 2],     a, vb[0], vb[1]);                                \
            mma16(o[np * 2 + 1], a, vb[2], vb[3]);                                \
        }                                                                         \
    }                                                                             \
    __syncthreads();                                                              \
} while (0)

    for (int kt = 0; kt < ntiles - 1; kt++) FLASH_TILE(kt, false);
    FLASH_TILE(ntiles - 1, true);

#undef FLASH_TILE
#undef KV_LOAD

    // epilogue: normalize, write y (fp16)
    const float il = 1.f / l_lo;
    const float ih = 1.f / l_hi;
    const size_t rl = (size_t)(b * T_ + qb * 64 + q0 + g);
#pragma unroll
    for (int nt = 0; nt < 16; nt++) {
        const int c = h * DH + nt * 8 + 2 * t;
        *(__half2*)&y[rl * D_MODEL + c]       = __floats2half2_rn(o[nt][0] * il, o[nt][1] * il);
        *(__half2*)&y[(rl + 8) * D_MODEL + c] = __floats2half2_rn(o[nt][2] * ih, o[nt][3] * ih);
    }
}

// ---------------------------------------------------------------------------
// Launch
// ---------------------------------------------------------------------------
extern "C" void kernel_launch(void* const* d_in, const int* in_sizes, int n_in,
                              void* d_out, int out_size) {
    const float* x        = (const float*)d_in[0];   // (2, 2048, 2048)
    const float* Wqkv     = (const float*)d_in[1];   // (2048, 3072)
    const float* Wo       = (const float*)d_in[2];   // (2048, 2048)
    const int*   startpos = (const int*)d_in[3];     // scalar
    float* out = (float*)d_out;                      // (2, 2048, 2048)

    __half *qkvh, *yh, *xh, *wqT, *woT;
    cudaGetSymbolAddress((void**)&qkvh, g_qkvh);
    cudaGetSymbolAddress((void**)&yh, g_yh);
    cudaGetSymbolAddress((void**)&xh, g_xh);
    cudaGetSymbolAddress((void**)&wqT, g_wqT);
    cudaGetSymbolAddress((void**)&woT, g_woT);

    cudaFuncSetAttribute((void*)gemm_h<true, true>,   cudaFuncAttributeMaxDynamicSharedMemorySize, GEMM_SMEM);
    cudaFuncSetAttribute((void*)gemm_h<false, false>, cudaFuncAttributeMaxDynamicSharedMemorySize, GEMM_SMEM);
    cudaFuncSetAttribute((void*)flash_h, cudaFuncAttributeMaxDynamicSharedMemorySize, FLASH_SMEM);

    // 0) pre-pass: fp16 conversions + weight transposes + rope table
    conv_h_kernel<<<(ROWS * D_MODEL / 4 + 255) / 256, 256>>>(x, (__half2*)xh, ROWS * D_MODEL / 4);
    transpose_h_kernel<<<dim3(QKV_DIM / 32, D_MODEL / 64), dim3(32, 8)>>>(Wqkv, wqT, D_MODEL, QKV_DIM);
    transpose_h_kernel<<<dim3(D_MODEL / 32, D_MODEL / 64), dim3(32, 8)>>>(Wo, woT, D_MODEL, D_MODEL);
    rope_table_kernel<<<T_ * 64 / 256, 256>>>(startpos);

    // 1) qkv = x @ Wqkv with fused RoPE (fp16 out)
    dim3 g1(QKV_DIM / 128, ROWS / 128);
    gemm_h<true, true><<<g1, 128, GEMM_SMEM>>>(xh, wqT, qkvh, ROWS, QKV_DIM, D_MODEL);

    // 2) flash attention -> yh (fp16)
    dim3 g3(T_ / 64, N_HEADS, B_);
    flash_h<<<g3, 128, FLASH_SMEM>>>(qkvh, yh);

    // 3) out = y @ Wo  (fp32 out)
    dim3 g4(D_MODEL / 128, ROWS / 128);
    gemm_h<false, false><<<g4, 128, GEMM_SMEM>>>(yh, woT, out, ROWS, D_MODEL, D_MODEL);
}

// round 16
// speedup vs baseline: 1.0855x; 1.0855x over previous
#include <cuda_runtime.h>
#include <cuda_fp16.h>
#include <math_constants.h>
#include <cstdint>

// Problem constants
#define D_MODEL   2048
#define N_HEADS   16
#define N_KV      4
#define DH        128
#define B_        2
#define T_        2048
#define QKV_DIM   3072          // 2048 + 2*4*128
#define ROWS      (B_*T_)       // 4096

// Scratch (static device allocations only)
__device__ __half  g_qkvh[ROWS * QKV_DIM];      // 24 MB
__device__ __half  g_yh  [ROWS * D_MODEL];      // 16 MB
__device__ __half  g_xh  [ROWS * D_MODEL];      // 16 MB  (fp16 x)
__device__ __half  g_wqT [QKV_DIM * D_MODEL];   // 12 MB  (fp16 Wqkv^T  [N][K])
__device__ __half  g_woT [D_MODEL * D_MODEL];   //  8 MB  (fp16 Wo^T    [N][K])
__device__ float2  g_rtab[T_ * 64];             //  1 MB  (cos/sin table)

// ---------------------------------------------------------------------------
// helpers
// ---------------------------------------------------------------------------
__device__ __forceinline__ void mma16(float c[4], const unsigned a[4],
                                      unsigned b0, unsigned b1) {
    asm volatile(
        "mma.sync.aligned.m16n8k16.row.col.f32.f16.f16.f32 "
        "{%0,%1,%2,%3},{%4,%5,%6,%7},{%8,%9},{%0,%1,%2,%3};"
        : "+f"(c[0]), "+f"(c[1]), "+f"(c[2]), "+f"(c[3])
        : "r"(a[0]), "r"(a[1]), "r"(a[2]), "r"(a[3]), "r"(b0), "r"(b1));
}

#define LDM4(d, addr) \
    asm volatile("ldmatrix.sync.aligned.m8n8.x4.shared.b16 {%0,%1,%2,%3}, [%4];" \
        : "=r"((d)[0]), "=r"((d)[1]), "=r"((d)[2]), "=r"((d)[3]) : "r"(addr))
#define LDM4T(d, addr) \
    asm volatile("ldmatrix.sync.aligned.m8n8.x4.trans.shared.b16 {%0,%1,%2,%3}, [%4];" \
        : "=r"((d)[0]), "=r"((d)[1]), "=r"((d)[2]), "=r"((d)[3]) : "r"(addr))

#define CPA16(dst_u32, src_ptr) \
    asm volatile("cp.async.cg.shared.global [%0], [%1], 16;" :: "r"(dst_u32), "l"(src_ptr))
#define CPA_COMMIT() asm volatile("cp.async.commit_group;")
#define CPA_WAIT(n)  asm volatile("cp.async.wait_group %0;" :: "n"(n))

__device__ __forceinline__ unsigned h2u(__half2 h) { return *(unsigned*)&h; }
__device__ __forceinline__ float ex2f(float x) {
    float r;
    asm("ex2.approx.ftz.f32 %0, %1;" : "=f"(r) : "f"(x));
    return r;
}

// ---------------------------------------------------------------------------
// merged pre-pass A: fp32->fp16 conversion of x  +  rope cos/sin table
// blocks [0, 8192): conv;  blocks [8192, 8704): rope table
// ---------------------------------------------------------------------------
__global__ __launch_bounds__(256) void prep_misc_kernel(const float* __restrict__ xin,
                                                        __half2* __restrict__ xout,
                                                        const int* __restrict__ start_pos) {
    if (blockIdx.x < 8192) {
        int i = blockIdx.x * 256 + threadIdx.x;          // < ROWS*D_MODEL/4
        float4 v = ((const float4*)xin)[i];
        xout[2 * i]     = __floats2half2_rn(v.x, v.y);
        xout[2 * i + 1] = __floats2half2_rn(v.z, v.w);
    } else {
        int id = (blockIdx.x - 8192) * 256 + threadIdx.x;  // < 2048*64
        int t = id >> 6, i = id & 63;
        float pos = (float)(start_pos[0] + t);
        float inv = exp2f(-(float)i * (13.287712379549449f / 64.0f));
        float ang = pos * inv;
        float s, c;
        sincosf(ang, &s, &c);
        g_rtab[id] = make_float2(c, s);
    }
}

// ---------------------------------------------------------------------------
// merged pre-pass B: transpose+convert both weights: W[K][N] fp32 -> WT[N][K] fp16
// z=0: Wqkv (N=3072, 96 n-blocks); z=1: Wo (N=2048, 64 n-blocks, guard)
// ---------------------------------------------------------------------------
__global__ __launch_bounds__(256) void transpose_h_kernel(const float* __restrict__ wq,
                                                          const float* __restrict__ wo) {
    __shared__ float tile[64][33];
    const float* in = blockIdx.z ? wo : wq;
    __half* out = blockIdx.z ? g_woT : g_wqT;
    const int N = blockIdx.z ? D_MODEL : QKV_DIM;
    if (blockIdx.z && blockIdx.x >= 64) return;
    const int K = D_MODEL;
    const int tx = threadIdx.x, ty = threadIdx.y;   // 32 x 8
    const int n0 = blockIdx.x * 32, k0 = blockIdx.y * 64;
#pragma unroll
    for (int jj = 0; jj < 8; jj++)
        tile[ty + 8 * jj][tx] = in[(size_t)(k0 + ty + 8 * jj) * N + n0 + tx];
    __syncthreads();
#pragma unroll
    for (int it = 0; it < 4; it++) {
        const int r = ty + 8 * it;                  // out row within n-tile
        __half2 h = __floats2half2_rn(tile[2 * tx][r], tile[2 * tx + 1][r]);
        *(__half2*)&out[(size_t)(n0 + r) * K + k0 + 2 * tx] = h;
    }
}

// ---------------------------------------------------------------------------
// fp16 GEMM: C[M,N] = A[M,K] @ BT[N][K]^T; fp32 accum.
// 128x128 CTA tile, 128 threads (4 warps, 64x64 warp tile), BK=64,
// 128B swizzled smem rows, cp.async THREE-stage pipeline, ldmatrix frags.
// ROPE: rotary embedding fused into epilogue for columns < 2560 (q,k regions).
// ---------------------------------------------------------------------------
#define G3STAGE 32768                    // bytes per stage (A 16K + B 16K)
#define GEMM_SMEM (3 * G3STAGE)          // 98304 bytes

template <bool HALF_OUT, bool ROPE>
__global__ __launch_bounds__(128) void gemm_h(const __half* __restrict__ A,
                                              const __half* __restrict__ Bt,
                                              void* __restrict__ Cv,
                                              int M, int N, int K) {
    extern __shared__ char smraw[];
    const unsigned sb = (unsigned)__cvta_generic_to_shared(smraw);

    const int tid = threadIdx.x;
    const int wid = tid >> 5, lane = tid & 31;
    const int g = lane >> 2, t = lane & 3;
    const int j = lane & 7, s1 = (lane >> 3) & 1, s2 = (lane >> 4) & 1;
    const int warp_m = (wid >> 1) * 64;
    const int warp_n = (wid & 1) * 64;
    const int bx = blockIdx.x, by = blockIdx.y;

    const unsigned a_base = (unsigned)((warp_m + s1 * 8 + j) * 128);
    const unsigned b_base = 16384u + (unsigned)((warp_n + s2 * 8 + j) * 128);
    const unsigned cxa = (unsigned)(s2 ^ j);
    const unsigned cxb = (unsigned)(s1 ^ j);

    const int lr = tid >> 3;             // 0..15
    const int c8 = tid & 7;              // 16B chunk in 128B row
    const unsigned lcx = (unsigned)(c8 ^ (lr & 7)) << 4;

    const int nst = K / 64;

    float acc[4][8][4];
#pragma unroll
    for (int i = 0; i < 4; i++)
#pragma unroll
        for (int jj = 0; jj < 8; jj++)
#pragma unroll
            for (int k = 0; k < 4; k++) acc[i][jj][k] = 0.f;

#define GLOAD(kt_) do {                                                          \
        const unsigned _tb = sb + ((kt_) % 3) * G3STAGE;                         \
        const int _ko = (kt_) * 64;                                              \
        _Pragma("unroll")                                                        \
        for (int p = 0; p < 8; p++) {                                            \
            const int r = lr + p * 16;                                           \
            CPA16(_tb + r * 128 + lcx, A + (size_t)(by * 128 + r) * K + _ko + c8 * 8); \
        }                                                                        \
        _Pragma("unroll")                                                        \
        for (int p = 0; p < 8; p++) {                                            \
            const int r = lr + p * 16;                                           \
            CPA16(_tb + 16384 + r * 128 + lcx, Bt + (size_t)(bx * 128 + r) * K + _ko + c8 * 8); \
        }                                                                        \
        CPA_COMMIT();                                                            \
    } while (0)

    GLOAD(0);
    GLOAD(1);

    for (int kt = 0; kt < nst; kt++) {
        CPA_WAIT(1);
        __syncthreads();
        if (kt + 2 < nst) GLOAD(kt + 2);

        const unsigned stg = sb + (kt % 3) * G3STAGE;
#pragma unroll
        for (int kk = 0; kk < 4; kk++) {
            unsigned af[4][4], bf[4][4];
#pragma unroll
            for (int mt = 0; mt < 4; mt++)
                LDM4(af[mt], stg + a_base + mt * 2048 + (((2u * kk) ^ cxa) << 4));
#pragma unroll
            for (int np = 0; np < 4; np++)
                LDM4(bf[np], stg + b_base + np * 2048 + (((2u * kk) ^ cxb) << 4));
#pragma unroll
            for (int mt = 0; mt < 4; mt++)
#pragma unroll
                for (int np = 0; np < 4; np++) {
                    mma16(acc[mt][np * 2],     af[mt], bf[np][0], bf[np][1]);
                    mma16(acc[mt][np * 2 + 1], af[mt], bf[np][2], bf[np][3]);
                }
        }
    }
#undef GLOAD

#pragma unroll
    for (int mt = 0; mt < 4; mt++) {
#pragma unroll
        for (int nt = 0; nt < 8; nt++) {
            const int r0 = by * 128 + warp_m + mt * 16 + g;
            const int c0 = bx * 128 + warp_n + nt * 8 + 2 * t;
            float v0 = acc[mt][nt][0], v1 = acc[mt][nt][1];
            float v2 = acc[mt][nt][2], v3 = acc[mt][nt][3];
            if (ROPE && c0 < 2560) {
                const int i = (c0 & 127) >> 1;
                float2 csA = g_rtab[(r0 & (T_ - 1)) * 64 + i];
                float2 csB = g_rtab[((r0 + 8) & (T_ - 1)) * 64 + i];
                float e0 = v0 * csA.x - v1 * csA.y;
                float o0 = v0 * csA.y + v1 * csA.x;
                float e1 = v2 * csB.x - v3 * csB.y;
                float o1 = v2 * csB.y + v3 * csB.x;
                v0 = e0; v1 = o0; v2 = e1; v3 = o1;
            }
            if (HALF_OUT) {
                __half* C = (__half*)Cv;
                *(__half2*)&C[(size_t)r0 * N + c0]       = __floats2half2_rn(v0, v1);
                *(__half2*)&C[(size_t)(r0 + 8) * N + c0] = __floats2half2_rn(v2, v3);
            } else {
                float* C = (float*)Cv;
                *(float2*)&C[(size_t)r0 * N + c0]       = make_float2(v0, v1);
                *(float2*)&C[(size_t)(r0 + 8) * N + c0] = make_float2(v2, v3);
            }
        }
    }
}

// ---------------------------------------------------------------------------
// Flash attention (causal, GQA), fp16 mma + ldmatrix, cp.async dbuf.
// 128 threads / 4 warps; q-tile 64 (16 rows/warp); kv-tile 64.
// Q fragments hoisted to registers; P in registers; diagonal tile peeled;
// ex2.approx softmax with fused scale; vote-skip O rescale.
// Grid: x = 32 (h,b) pairs, y = 32 q-blocks REVERSED (global longest-first).
// smem bytes: Qs[64][272B] @0 | Ks 2x[64][272B] @17408 | Vs 2x[64][256B sw] @52224
// ---------------------------------------------------------------------------
#define FQ_OFF 0u
#define FK_OFF 17408u
#define FV_OFF 52224u
#define FLASH_SMEM 84992

__global__ __launch_bounds__(128, 2) void flash_h(const __half* __restrict__ qkv,
                                                  __half* __restrict__ y) {
    extern __shared__ char smraw[];
    const unsigned sb = (unsigned)__cvta_generic_to_shared(smraw);

    const int tid = threadIdx.x;
    const int wid = tid >> 5, lane = tid & 31;
    const int g = lane >> 2, t = lane & 3;
    const int j = lane & 7, s1 = (lane >> 3) & 1, s2 = (lane >> 4) & 1;
    const int h = blockIdx.x & 15, b = blockIdx.x >> 4;
    const int qb = gridDim.y - 1 - blockIdx.y;   // longest blocks first, globally
    const int kvh = h >> 2;
    const int q0 = wid * 16;
    const float SC = 0.08838834764831845f * 1.4426950408889634f;  // scale*log2(e)

    const unsigned q_lane = FQ_OFF + (unsigned)((q0 + s1 * 8 + j) * 272 + s2 * 16);
    const unsigned k_lane = FK_OFF + (unsigned)((s2 * 8 + j) * 272 + s1 * 16);
    const unsigned vrow   = (unsigned)((s1 * 8 + j) * 256);

    const int lrow8 = tid >> 4;          // 0..7
    const int lc = tid & 15;             // 16B chunk within row

    // Q tile (group A): 64 rows x 16 chunks
#pragma unroll
    for (int it = 0; it < 8; it++) {
        const int row = it * 8 + lrow8;
        CPA16(sb + FQ_OFF + row * 272 + lc * 16,
              qkv + (size_t)(b * T_ + qb * 64 + row) * QKV_DIM + h * DH + lc * 8);
    }
    CPA_COMMIT();

    const int ntiles = qb + 1;

#define KV_LOAD(kt_) do {                                                        \
        const unsigned _stg = (unsigned)((kt_) & 1);                             \
        _Pragma("unroll")                                                        \
        for (int it = 0; it < 8; it++) {                                         \
            const int row = it * 8 + lrow8;                                      \
            const __half* gp = qkv + (size_t)(b * T_ + (kt_) * 64 + row) * QKV_DIM \
                               + D_MODEL + kvh * DH + lc * 8;                    \
            CPA16(sb + FK_OFF + _stg * 17408 + row * 272 + lc * 16, gp);         \
            CPA16(sb + FV_OFF + _stg * 16384 + row * 256 + ((lc ^ (row & 7)) << 4), gp + N_KV * DH); \
        }                                                                        \
        CPA_COMMIT();                                                            \
    } while (0)

    KV_LOAD(0);

    // hoist Q fragments to registers (Q group done once <=1 group pending)
    unsigned qf[8][4];
    CPA_WAIT(1);
    __syncthreads();
#pragma unroll
    for (int kk = 0; kk < 8; kk++)
        LDM4(qf[kk], sb + q_lane + kk * 32);

    float m_lo = -1e30f, m_hi = -1e30f, l_lo = 0.f, l_hi = 0.f;
    float o[16][4];
#pragma unroll
    for (int i = 0; i < 16; i++)
#pragma unroll
        for (int jj = 0; jj < 4; jj++) o[i][jj] = 0.f;

#define FLASH_TILE(kt_, MASKED) do {                                              \
    if ((kt_) + 1 < ntiles) { KV_LOAD((kt_) + 1); CPA_WAIT(1); }                  \
    else                    { CPA_WAIT(0); }                                      \
    __syncthreads();                                                              \
    const unsigned kstg = ((kt_) & 1) * 17408;                                    \
    const unsigned vstg = FV_OFF + ((kt_) & 1) * 16384;                           \
    float s[8][4];                                                                \
    _Pragma("unroll")                                                             \
    for (int nt = 0; nt < 8; nt++) { s[nt][0]=0.f; s[nt][1]=0.f; s[nt][2]=0.f; s[nt][3]=0.f; } \
    _Pragma("unroll")                                                             \
    for (int kk = 0; kk < 8; kk++) {                                              \
        _Pragma("unroll")                                                         \
        for (int np = 0; np < 4; np++) {                                          \
            unsigned kb[4];                                                       \
            LDM4(kb, sb + k_lane + kstg + np * 4352 + kk * 32);                   \
            mma16(s[np * 2],     qf[kk], kb[0], kb[1]);                           \
            mma16(s[np * 2 + 1], qf[kk], kb[2], kb[3]);                           \
        }                                                                         \
    }                                                                             \
    float ml = -1e30f, mh = -1e30f;                                               \
    if (MASKED) {                                                                 \
        const int rlo = qb * 64 + q0 + g;                                         \
        const int rhi = rlo + 8;                                                  \
        const int cb = (kt_) * 64;                                                \
        _Pragma("unroll")                                                         \
        for (int nt = 0; nt < 8; nt++) {                                          \
            const int c0 = cb + nt * 8 + 2 * t, c1 = c0 + 1;                      \
            if (c0 > rlo) s[nt][0] = -1e30f;                                      \
            if (c1 > rlo) s[nt][1] = -1e30f;                                      \
            if (c0 > rhi) s[nt][2] = -1e30f;                                      \
            if (c1 > rhi) s[nt][3] = -1e30f;                                      \
        }                                                                         \
    }                                                                             \
    _Pragma("unroll")                                                             \
    for (int nt = 0; nt < 8; nt++) {                                              \
        ml = fmaxf(ml, fmaxf(s[nt][0], s[nt][1]));                                \
        mh = fmaxf(mh, fmaxf(s[nt][2], s[nt][3]));                                \
    }                                                                             \
    ml = fmaxf(ml, __shfl_xor_sync(0xffffffffu, ml, 1));                          \
    ml = fmaxf(ml, __shfl_xor_sync(0xffffffffu, ml, 2));                          \
    mh = fmaxf(mh, __shfl_xor_sync(0xffffffffu, mh, 1));                          \
    mh = fmaxf(mh, __shfl_xor_sync(0xffffffffu, mh, 2));                          \
    const float mnl = fmaxf(m_lo, ml);                                            \
    const float mnh = fmaxf(m_hi, mh);                                            \
    const float nbl = -mnl * SC;                                                  \
    const float nbh = -mnh * SC;                                                  \
    float ll = 0.f, lh = 0.f;                                                     \
    _Pragma("unroll")                                                             \
    for (int nt = 0; nt < 8; nt++) {                                              \
        s[nt][0] = ex2f(fmaf(s[nt][0], SC, nbl));                                 \
        s[nt][1] = ex2f(fmaf(s[nt][1], SC, nbl));                                 \
        s[nt][2] = ex2f(fmaf(s[nt][2], SC, nbh));                                 \
        s[nt][3] = ex2f(fmaf(s[nt][3], SC, nbh));                                 \
        ll += s[nt][0] + s[nt][1];                                                \
        lh += s[nt][2] + s[nt][3];                                                \
    }                                                                             \
    ll += __shfl_xor_sync(0xffffffffu, ll, 1);                                    \
    ll += __shfl_xor_sync(0xffffffffu, ll, 2);                                    \
    lh += __shfl_xor_sync(0xffffffffu, lh, 1);                                    \
    lh += __shfl_xor_sync(0xffffffffu, lh, 2);                                    \
    if (__all_sync(0xffffffffu, (mnl == m_lo) & (mnh == m_hi))) {                 \
        l_lo += ll; l_hi += lh;                                                   \
    } else {                                                                      \
        const float al = ex2f((m_lo - mnl) * SC);                                 \
        const float ah = ex2f((m_hi - mnh) * SC);                                 \
        l_lo = l_lo * al + ll;                                                    \
        l_hi = l_hi * ah + lh;                                                    \
        _Pragma("unroll")                                                         \
        for (int nt = 0; nt < 16; nt++) {                                         \
            o[nt][0] *= al; o[nt][1] *= al;                                       \
            o[nt][2] *= ah; o[nt][3] *= ah;                                       \
        }                                                                         \
    }                                                                             \
    m_lo = mnl; m_hi = mnh;                                                       \
    _Pragma("unroll")                                                             \
    for (int kk = 0; kk < 4; kk++) {                                              \
        unsigned a[4];                                                            \
        a[0] = h2u(__floats2half2_rn(s[2 * kk][0],     s[2 * kk][1]));            \
        a[1] = h2u(__floats2half2_rn(s[2 * kk][2],     s[2 * kk][3]));            \
        a[2] = h2u(__floats2half2_rn(s[2 * kk + 1][0], s[2 * kk + 1][1]));        \
        a[3] = h2u(__floats2half2_rn(s[2 * kk + 1][2], s[2 * kk + 1][3]));        \
        _Pragma("unroll")                                                         \
        for (int np = 0; np < 8; np++) {                                          \
            unsigned vb[4];                                                       \
            const unsigned chunk = (unsigned)(((np << 1) | s2) ^ j);              \
            LDM4T(vb, sb + vstg + kk * 4096 + vrow + (chunk << 4));               \
            mma16(o[np * 2],     a, vb[0], vb[1]);                                \
            mma16(o[np * 2 + 1], a, vb[2], vb[3]);                                \
        }                                                                         \
    }                                                                             \
    __syncthreads();                                                              \
} while (0)

    for (int kt = 0; kt < ntiles - 1; kt++) FLASH_TILE(kt, false);
    FLASH_TILE(ntiles - 1, true);

#undef FLASH_TILE
#undef KV_LOAD

    // epilogue: normalize, write y (fp16)
    const float il = 1.f / l_lo;
    const float ih = 1.f / l_hi;
    const size_t rl = (size_t)(b * T_ + qb * 64 + q0 + g);
#pragma unroll
    for (int nt = 0; nt < 16; nt++) {
        const int c = h * DH + nt * 8 + 2 * t;
        *(__half2*)&y[rl * D_MODEL + c]       = __floats2half2_rn(o[nt][0] * il, o[nt][1] * il);
        *(__half2*)&y[(rl + 8) * D_MODEL + c] = __floats2half2_rn(o[nt][2] * ih, o[nt][3] * ih);
    }
}

// ---------------------------------------------------------------------------
// Launch
// ---------------------------------------------------------------------------
extern "C" void kernel_launch(void* const* d_in, const int* in_sizes, int n_in,
                              void* d_out, int out_size) {
    const float* x        = (const float*)d_in[0];   // (2, 2048, 2048)
    const float* Wqkv     = (const float*)d_in[1];   // (2048, 3072)
    const float* Wo       = (const float*)d_in[2];   // (2048, 2048)
    const int*   startpos = (const int*)d_in[3];     // scalar
    float* out = (float*)d_out;                      // (2, 2048, 2048)

    __half *qkvh, *yh, *xh, *wqT, *woT;
    cudaGetSymbolAddress((void**)&qkvh, g_qkvh);
    cudaGetSymbolAddress((void**)&yh, g_yh);
    cudaGetSymbolAddress((void**)&xh, g_xh);
    cudaGetSymbolAddress((void**)&wqT, g_wqT);
    cudaGetSymbolAddress((void**)&woT, g_woT);

    cudaFuncSetAttribute((void*)gemm_h<true, true>,   cudaFuncAttributeMaxDynamicSharedMemorySize, GEMM_SMEM);
    cudaFuncSetAttribute((void*)gemm_h<false, false>, cudaFuncAttributeMaxDynamicSharedMemorySize, GEMM_SMEM);
    cudaFuncSetAttribute((void*)flash_h, cudaFuncAttributeMaxDynamicSharedMemorySize, FLASH_SMEM);

    // 0) pre-pass: (x conv + rope table) and (both weight transposes)
    prep_misc_kernel<<<8704, 256>>>(x, (__half2*)xh, startpos);
    transpose_h_kernel<<<dim3(QKV_DIM / 32, D_MODEL / 64, 2), dim3(32, 8)>>>(Wqkv, Wo);

    // 1) qkv = x @ Wqkv with fused RoPE (fp16 out)
    dim3 g1(QKV_DIM / 128, ROWS / 128);
    gemm_h<true, true><<<g1, 128, GEMM_SMEM>>>(xh, wqT, qkvh, ROWS, QKV_DIM, D_MODEL);

    // 2) flash attention -> yh (fp16); x = (h,b), y = q-blocks (reversed in-kernel)
    dim3 g3(N_HEADS * B_, T_ / 64, 1);
    flash_h<<<g3, 128, FLASH_SMEM>>>(qkvh, yh);

    // 3) out = y @ Wo  (fp32 out)
    dim3 g4(D_MODEL / 128, ROWS / 128);
    gemm_h<false, false><<<g4, 128, GEMM_SMEM>>>(yh, woT, out, ROWS, D_MODEL, D_MODEL);
}

// round 17
// speedup vs baseline: 1.0910x; 1.0050x over previous
#include <cuda_runtime.h>
#include <cuda_fp16.h>
#include <math_constants.h>
#include <cstdint>

// Problem constants
#define D_MODEL   2048
#define N_HEADS   16
#define N_KV      4
#define DH        128
#define B_        2
#define T_        2048
#define QKV_DIM   3072          // 2048 + 2*4*128
#define ROWS      (B_*T_)       // 4096

// Scratch (static device allocations only)
__device__ __half  g_qkvh[ROWS * QKV_DIM];      // 24 MB
__device__ __half  g_yh  [ROWS * D_MODEL];      // 16 MB
__device__ __half  g_xh  [ROWS * D_MODEL];      // 16 MB  (fp16 x)
__device__ __half  g_wqT [QKV_DIM * D_MODEL];   // 12 MB  (fp16 Wqkv^T  [N][K])
__device__ __half  g_woT [D_MODEL * D_MODEL];   //  8 MB  (fp16 Wo^T    [N][K])
__device__ float2  g_rtab[T_ * 64];             //  1 MB  (cos/sin table)

// ---------------------------------------------------------------------------
// helpers
// ---------------------------------------------------------------------------
__device__ __forceinline__ void mma16(float c[4], const unsigned a[4],
                                      unsigned b0, unsigned b1) {
    asm volatile(
        "mma.sync.aligned.m16n8k16.row.col.f32.f16.f16.f32 "
        "{%0,%1,%2,%3},{%4,%5,%6,%7},{%8,%9},{%0,%1,%2,%3};"
        : "+f"(c[0]), "+f"(c[1]), "+f"(c[2]), "+f"(c[3])
        : "r"(a[0]), "r"(a[1]), "r"(a[2]), "r"(a[3]), "r"(b0), "r"(b1));
}

#define LDM4(d, addr) \
    asm volatile("ldmatrix.sync.aligned.m8n8.x4.shared.b16 {%0,%1,%2,%3}, [%4];" \
        : "=r"((d)[0]), "=r"((d)[1]), "=r"((d)[2]), "=r"((d)[3]) : "r"(addr))
#define LDM4T(d, addr) \
    asm volatile("ldmatrix.sync.aligned.m8n8.x4.trans.shared.b16 {%0,%1,%2,%3}, [%4];" \
        : "=r"((d)[0]), "=r"((d)[1]), "=r"((d)[2]), "=r"((d)[3]) : "r"(addr))

#define CPA16(dst_u32, src_ptr) \
    asm volatile("cp.async.cg.shared.global [%0], [%1], 16;" :: "r"(dst_u32), "l"(src_ptr))
#define CPA_COMMIT() asm volatile("cp.async.commit_group;")
#define CPA_WAIT(n)  asm volatile("cp.async.wait_group %0;" :: "n"(n))

__device__ __forceinline__ unsigned h2u(__half2 h) { return *(unsigned*)&h; }
__device__ __forceinline__ float ex2f(float x) {
    float r;
    asm("ex2.approx.ftz.f32 %0, %1;" : "=f"(r) : "f"(x));
    return r;
}

// ---------------------------------------------------------------------------
// merged pre-pass A: fp32->fp16 conversion of x  +  rope cos/sin table
// ---------------------------------------------------------------------------
__global__ __launch_bounds__(256) void prep_misc_kernel(const float* __restrict__ xin,
                                                        __half2* __restrict__ xout,
                                                        const int* __restrict__ start_pos) {
    if (blockIdx.x < 8192) {
        int i = blockIdx.x * 256 + threadIdx.x;          // < ROWS*D_MODEL/4
        float4 v = ((const float4*)xin)[i];
        xout[2 * i]     = __floats2half2_rn(v.x, v.y);
        xout[2 * i + 1] = __floats2half2_rn(v.z, v.w);
    } else {
        int id = (blockIdx.x - 8192) * 256 + threadIdx.x;  // < 2048*64
        int t = id >> 6, i = id & 63;
        float pos = (float)(start_pos[0] + t);
        float inv = exp2f(-(float)i * (13.287712379549449f / 64.0f));
        float ang = pos * inv;
        float s, c;
        sincosf(ang, &s, &c);
        g_rtab[id] = make_float2(c, s);
    }
}

// ---------------------------------------------------------------------------
// merged pre-pass B: transpose+convert both weights
// ---------------------------------------------------------------------------
__global__ __launch_bounds__(256) void transpose_h_kernel(const float* __restrict__ wq,
                                                          const float* __restrict__ wo) {
    __shared__ float tile[64][33];
    const float* in = blockIdx.z ? wo : wq;
    __half* out = blockIdx.z ? g_woT : g_wqT;
    const int N = blockIdx.z ? D_MODEL : QKV_DIM;
    if (blockIdx.z && blockIdx.x >= 64) return;
    const int K = D_MODEL;
    const int tx = threadIdx.x, ty = threadIdx.y;   // 32 x 8
    const int n0 = blockIdx.x * 32, k0 = blockIdx.y * 64;
#pragma unroll
    for (int jj = 0; jj < 8; jj++)
        tile[ty + 8 * jj][tx] = in[(size_t)(k0 + ty + 8 * jj) * N + n0 + tx];
    __syncthreads();
#pragma unroll
    for (int it = 0; it < 4; it++) {
        const int r = ty + 8 * it;
        __half2 h = __floats2half2_rn(tile[2 * tx][r], tile[2 * tx + 1][r]);
        *(__half2*)&out[(size_t)(n0 + r) * K + k0 + 2 * tx] = h;
    }
}

// ---------------------------------------------------------------------------
// fp16 GEMM (unchanged from round 16)
// ---------------------------------------------------------------------------
#define G3STAGE 32768
#define GEMM_SMEM (3 * G3STAGE)          // 98304 bytes

template <bool HALF_OUT, bool ROPE>
__global__ __launch_bounds__(128) void gemm_h(const __half* __restrict__ A,
                                              const __half* __restrict__ Bt,
                                              void* __restrict__ Cv,
                                              int M, int N, int K) {
    extern __shared__ char smraw[];
    const unsigned sb = (unsigned)__cvta_generic_to_shared(smraw);

    const int tid = threadIdx.x;
    const int wid = tid >> 5, lane = tid & 31;
    const int g = lane >> 2, t = lane & 3;
    const int j = lane & 7, s1 = (lane >> 3) & 1, s2 = (lane >> 4) & 1;
    const int warp_m = (wid >> 1) * 64;
    const int warp_n = (wid & 1) * 64;
    const int bx = blockIdx.x, by = blockIdx.y;

    const unsigned a_base = (unsigned)((warp_m + s1 * 8 + j) * 128);
    const unsigned b_base = 16384u + (unsigned)((warp_n + s2 * 8 + j) * 128);
    const unsigned cxa = (unsigned)(s2 ^ j);
    const unsigned cxb = (unsigned)(s1 ^ j);

    const int lr = tid >> 3;
    const int c8 = tid & 7;
    const unsigned lcx = (unsigned)(c8 ^ (lr & 7)) << 4;

    const int nst = K / 64;

    float acc[4][8][4];
#pragma unroll
    for (int i = 0; i < 4; i++)
#pragma unroll
        for (int jj = 0; jj < 8; jj++)
#pragma unroll
            for (int k = 0; k < 4; k++) acc[i][jj][k] = 0.f;

#define GLOAD(kt_) do {                                                          \
        const unsigned _tb = sb + ((kt_) % 3) * G3STAGE;                         \
        const int _ko = (kt_) * 64;                                              \
        _Pragma("unroll")                                                        \
        for (int p = 0; p < 8; p++) {                                            \
            const int r = lr + p * 16;                                           \
            CPA16(_tb + r * 128 + lcx, A + (size_t)(by * 128 + r) * K + _ko + c8 * 8); \
        }                                                                        \
        _Pragma("unroll")                                                        \
        for (int p = 0; p < 8; p++) {                                            \
            const int r = lr + p * 16;                                           \
            CPA16(_tb + 16384 + r * 128 + lcx, Bt + (size_t)(bx * 128 + r) * K + _ko + c8 * 8); \
        }                                                                        \
        CPA_COMMIT();                                                            \
    } while (0)

    GLOAD(0);
    GLOAD(1);

    for (int kt = 0; kt < nst; kt++) {
        CPA_WAIT(1);
        __syncthreads();
        if (kt + 2 < nst) GLOAD(kt + 2);

        const unsigned stg = sb + (kt % 3) * G3STAGE;
#pragma unroll
        for (int kk = 0; kk < 4; kk++) {
            unsigned af[4][4], bf[4][4];
#pragma unroll
            for (int mt = 0; mt < 4; mt++)
                LDM4(af[mt], stg + a_base + mt * 2048 + (((2u * kk) ^ cxa) << 4));
#pragma unroll
            for (int np = 0; np < 4; np++)
                LDM4(bf[np], stg + b_base + np * 2048 + (((2u * kk) ^ cxb) << 4));
#pragma unroll
            for (int mt = 0; mt < 4; mt++)
#pragma unroll
                for (int np = 0; np < 4; np++) {
                    mma16(acc[mt][np * 2],     af[mt], bf[np][0], bf[np][1]);
                    mma16(acc[mt][np * 2 + 1], af[mt], bf[np][2], bf[np][3]);
                }
        }
    }
#undef GLOAD

#pragma unroll
    for (int mt = 0; mt < 4; mt++) {
#pragma unroll
        for (int nt = 0; nt < 8; nt++) {
            const int r0 = by * 128 + warp_m + mt * 16 + g;
            const int c0 = bx * 128 + warp_n + nt * 8 + 2 * t;
            float v0 = acc[mt][nt][0], v1 = acc[mt][nt][1];
            float v2 = acc[mt][nt][2], v3 = acc[mt][nt][3];
            if (ROPE && c0 < 2560) {
                const int i = (c0 & 127) >> 1;
                float2 csA = g_rtab[(r0 & (T_ - 1)) * 64 + i];
                float2 csB = g_rtab[((r0 + 8) & (T_ - 1)) * 64 + i];
                float e0 = v0 * csA.x - v1 * csA.y;
                float o0 = v0 * csA.y + v1 * csA.x;
                float e1 = v2 * csB.x - v3 * csB.y;
                float o1 = v2 * csB.y + v3 * csB.x;
                v0 = e0; v1 = o0; v2 = e1; v3 = o1;
            }
            if (HALF_OUT) {
                __half* C = (__half*)Cv;
                *(__half2*)&C[(size_t)r0 * N + c0]       = __floats2half2_rn(v0, v1);
                *(__half2*)&C[(size_t)(r0 + 8) * N + c0] = __floats2half2_rn(v2, v3);
            } else {
                float* C = (float*)Cv;
                *(float2*)&C[(size_t)r0 * N + c0]       = make_float2(v0, v1);
                *(float2*)&C[(size_t)(r0 + 8) * N + c0] = make_float2(v2, v3);
            }
        }
    }
}

// ---------------------------------------------------------------------------
// Flash attention (causal, GQA), fp16 mma + ldmatrix.
// SOFTWARE-PIPELINED: QK(kt+1) -> s_next overlaps softmax(kt)+PV(kt) on s_cur.
// K: 3 stages @ 0/17408/34816 (Q staged through K-stage-2 then hoisted);
// V: 2 stages @ 52224/68608.  smem total 84992 (2 CTAs/SM).
// Loads per iter: {K(kt+2), V(kt+1)} one group; wait_group(1).
// l-sum shfl reductions deferred until after PV mmas.
// Grid: x = 32 (h,b), y = q-blocks reversed (global longest-first).
// ---------------------------------------------------------------------------
#define FV_OFF 52224u
#define FLASH_SMEM 84992

__global__ __launch_bounds__(128, 2) void flash_h(const __half* __restrict__ qkv,
                                                  __half* __restrict__ y) {
    extern __shared__ char smraw[];
    const unsigned sb = (unsigned)__cvta_generic_to_shared(smraw);

    const int tid = threadIdx.x;
    const int wid = tid >> 5, lane = tid & 31;
    const int g = lane >> 2, t = lane & 3;
    const int j = lane & 7, s1 = (lane >> 3) & 1, s2 = (lane >> 4) & 1;
    const int h = blockIdx.x & 15, b = blockIdx.x >> 4;
    const int qb = gridDim.y - 1 - blockIdx.y;   // longest blocks first, globally
    const int kvh = h >> 2;
    const int q0 = wid * 16;
    const float SC = 0.08838834764831845f * 1.4426950408889634f;  // scale*log2(e)

    // Q staged in K-stage-2 region (34816), 272B pitch
    const unsigned q_lane = 34816u + (unsigned)((q0 + s1 * 8 + j) * 272 + s2 * 16);
    const unsigned k_lane = (unsigned)((s2 * 8 + j) * 272 + s1 * 16);
    const unsigned vrow   = (unsigned)((s1 * 8 + j) * 256);

    const int lrow8 = tid >> 4;          // 0..7
    const int lc = tid & 15;             // 16B chunk within row

    const int ntiles = qb + 1;

#define K_LOAD(kt_) do {                                                         \
        const unsigned _ks = ((unsigned)(kt_) % 3u) * 17408u;                    \
        _Pragma("unroll")                                                        \
        for (int it = 0; it < 8; it++) {                                         \
            const int row = it * 8 + lrow8;                                      \
            CPA16(sb + _ks + row * 272 + lc * 16,                                \
                  qkv + (size_t)(b * T_ + (kt_) * 64 + row) * QKV_DIM            \
                  + D_MODEL + kvh * DH + lc * 8);                                \
        }                                                                        \
    } while (0)

#define V_LOAD(kt_) do {                                                         \
        const unsigned _vs = FV_OFF + ((unsigned)(kt_) & 1u) * 16384u;           \
        _Pragma("unroll")                                                        \
        for (int it = 0; it < 8; it++) {                                         \
            const int row = it * 8 + lrow8;                                      \
            CPA16(sb + _vs + row * 256 + ((lc ^ (row & 7)) << 4),                \
                  qkv + (size_t)(b * T_ + (kt_) * 64 + row) * QKV_DIM            \
                  + D_MODEL + N_KV * DH + kvh * DH + lc * 8);                    \
        }                                                                        \
    } while (0)

    // prologue group A: Q -> K-stage-2, K(0) -> K-stage-0
#pragma unroll
    for (int it = 0; it < 8; it++) {
        const int row = it * 8 + lrow8;
        CPA16(sb + 34816u + row * 272 + lc * 16,
              qkv + (size_t)(b * T_ + qb * 64 + row) * QKV_DIM + h * DH + lc * 8);
    }
    K_LOAD(0);
    CPA_COMMIT();

    // prologue group B: K(1), V(0)
    if (1 < ntiles) K_LOAD(1);
    V_LOAD(0);
    CPA_COMMIT();

    CPA_WAIT(1);          // group A done (Q, K0); group B may be in flight
    __syncthreads();

    // hoist Q fragments
    unsigned qf[8][4];
#pragma unroll
    for (int kk = 0; kk < 8; kk++)
        LDM4(qf[kk], sb + q_lane + kk * 32);

#define QK_TILE(kt1_, SD) do {                                                   \
    const unsigned _kq = ((unsigned)(kt1_) % 3u) * 17408u;                       \
    _Pragma("unroll")                                                            \
    for (int nt = 0; nt < 8; nt++) { SD[nt][0]=0.f; SD[nt][1]=0.f; SD[nt][2]=0.f; SD[nt][3]=0.f; } \
    _Pragma("unroll")                                                            \
    for (int kk = 0; kk < 8; kk++) {                                             \
        _Pragma("unroll")                                                        \
        for (int np = 0; np < 4; np++) {                                         \
            unsigned kb[4];                                                      \
            LDM4(kb, sb + k_lane + _kq + np * 4352 + kk * 32);                   \
            mma16(SD[np * 2],     qf[kk], kb[0], kb[1]);                         \
            mma16(SD[np * 2 + 1], qf[kk], kb[2], kb[3]);                         \
        }                                                                        \
    }                                                                            \
} while (0)

    float sA[8][4], sB[8][4];
    QK_TILE(0, sA);       // reads K-stage-0 (group A, landed)
    __syncthreads();      // Q region (K-stage-2) free before K(2) load at iter 0

    float m_lo = -1e30f, m_hi = -1e30f, l_lo = 0.f, l_hi = 0.f;
    float o[16][4];
#pragma unroll
    for (int i = 0; i < 16; i++)
#pragma unroll
        for (int jj = 0; jj < 4; jj++) o[i][jj] = 0.f;

#define FLASH_TILE(kt_, SCUR, SNXT) do {                                          \
    if ((kt_) + 2 < ntiles) K_LOAD((kt_) + 2);                                    \
    if ((kt_) + 1 < ntiles) V_LOAD((kt_) + 1);                                    \
    CPA_COMMIT();                                                                 \
    CPA_WAIT(1);                                                                  \
    __syncthreads();                                                              \
    if ((kt_) + 1 < ntiles) QK_TILE((kt_) + 1, SNXT);                             \
    if ((kt_) == ntiles - 1) {                                                    \
        const int rlo = qb * 64 + q0 + g;                                         \
        const int rhi = rlo + 8;                                                  \
        const int cb = (kt_) * 64;                                                \
        _Pragma("unroll")                                                         \
        for (int nt = 0; nt < 8; nt++) {                                          \
            const int c0 = cb + nt * 8 + 2 * t, c1 = c0 + 1;                      \
            if (c0 > rlo) SCUR[nt][0] = -1e30f;                                   \
            if (c1 > rlo) SCUR[nt][1] = -1e30f;                                   \
            if (c0 > rhi) SCUR[nt][2] = -1e30f;                                   \
            if (c1 > rhi) SCUR[nt][3] = -1e30f;                                   \
        }                                                                         \
    }                                                                             \
    float ml = -1e30f, mh = -1e30f;                                               \
    _Pragma("unroll")                                                             \
    for (int nt = 0; nt < 8; nt++) {                                              \
        ml = fmaxf(ml, fmaxf(SCUR[nt][0], SCUR[nt][1]));                          \
        mh = fmaxf(mh, fmaxf(SCUR[nt][2], SCUR[nt][3]));                          \
    }                                                                             \
    ml = fmaxf(ml, __shfl_xor_sync(0xffffffffu, ml, 1));                          \
    ml = fmaxf(ml, __shfl_xor_sync(0xffffffffu, ml, 2));                          \
    mh = fmaxf(mh, __shfl_xor_sync(0xffffffffu, mh, 1));                          \
    mh = fmaxf(mh, __shfl_xor_sync(0xffffffffu, mh, 2));                          \
    const float mnl = fmaxf(m_lo, ml);                                            \
    const float mnh = fmaxf(m_hi, mh);                                            \
    const float nbl = -mnl * SC;                                                  \
    const float nbh = -mnh * SC;                                                  \
    float ll = 0.f, lh = 0.f;                                                     \
    _Pragma("unroll")                                                             \
    for (int nt = 0; nt < 8; nt++) {                                              \
        SCUR[nt][0] = ex2f(fmaf(SCUR[nt][0], SC, nbl));                           \
        SCUR[nt][1] = ex2f(fmaf(SCUR[nt][1], SC, nbl));                           \
        SCUR[nt][2] = ex2f(fmaf(SCUR[nt][2], SC, nbh));                           \
        SCUR[nt][3] = ex2f(fmaf(SCUR[nt][3], SC, nbh));                           \
        ll += SCUR[nt][0] + SCUR[nt][1];                                          \
        lh += SCUR[nt][2] + SCUR[nt][3];                                          \
    }                                                                             \
    if (!__all_sync(0xffffffffu, (mnl == m_lo) & (mnh == m_hi))) {                \
        const float al = ex2f((m_lo - mnl) * SC);                                 \
        const float ah = ex2f((m_hi - mnh) * SC);                                 \
        l_lo *= al; l_hi *= ah;                                                   \
        _Pragma("unroll")                                                         \
        for (int nt = 0; nt < 16; nt++) {                                         \
            o[nt][0] *= al; o[nt][1] *= al;                                       \
            o[nt][2] *= ah; o[nt][3] *= ah;                                       \
        }                                                                         \
    }                                                                             \
    m_lo = mnl; m_hi = mnh;                                                       \
    const unsigned vstg = FV_OFF + ((unsigned)(kt_) & 1u) * 16384u;               \
    _Pragma("unroll")                                                             \
    for (int kk = 0; kk < 4; kk++) {                                              \
        unsigned a[4];                                                            \
        a[0] = h2u(__floats2half2_rn(SCUR[2 * kk][0],     SCUR[2 * kk][1]));      \
        a[1] = h2u(__floats2half2_rn(SCUR[2 * kk][2],     SCUR[2 * kk][3]));      \
        a[2] = h2u(__floats2half2_rn(SCUR[2 * kk + 1][0], SCUR[2 * kk + 1][1]));  \
        a[3] = h2u(__floats2half2_rn(SCUR[2 * kk + 1][2], SCUR[2 * kk + 1][3]));  \
        _Pragma("unroll")                                                         \
        for (int np = 0; np < 8; np++) {                                          \
            unsigned vb[4];                                                       \
            const unsigned chunk = (unsigned)(((np << 1) | s2) ^ j);              \
            LDM4T(vb, sb + vstg + kk * 4096 + vrow + (chunk << 4));               \
            mma16(o[np * 2],     a, vb[0], vb[1]);                                \
            mma16(o[np * 2 + 1], a, vb[2], vb[3]);                                \
        }                                                                         \
    }                                                                             \
    ll += __shfl_xor_sync(0xffffffffu, ll, 1);                                    \
    ll += __shfl_xor_sync(0xffffffffu, ll, 2);                                    \
    lh += __shfl_xor_sync(0xffffffffu, lh, 1);                                    \
    lh += __shfl_xor_sync(0xffffffffu, lh, 2);                                    \
    l_lo += ll; l_hi += lh;                                                       \
    __syncthreads();                                                              \
} while (0)

    for (int kt = 0; kt < ntiles; kt++) {
        if (kt & 1) FLASH_TILE(kt, sB, sA);
        else        FLASH_TILE(kt, sA, sB);
    }

#undef FLASH_TILE
#undef QK_TILE
#undef K_LOAD
#undef V_LOAD

    // epilogue: normalize, write y (fp16)
    const float il = 1.f / l_lo;
    const float ih = 1.f / l_hi;
    const size_t rl = (size_t)(b * T_ + qb * 64 + q0 + g);
#pragma unroll
    for (int nt = 0; nt < 16; nt++) {
        const int c = h * DH + nt * 8 + 2 * t;
        *(__half2*)&y[rl * D_MODEL + c]       = __floats2half2_rn(o[nt][0] * il, o[nt][1] * il);
        *(__half2*)&y[(rl + 8) * D_MODEL + c] = __floats2half2_rn(o[nt][2] * ih, o[nt][3] * ih);
    }
}

// ---------------------------------------------------------------------------
// Launch
// ---------------------------------------------------------------------------
extern "C" void kernel_launch(void* const* d_in, const int* in_sizes, int n_in,
                              void* d_out, int out_size) {
    const float* x        = (const float*)d_in[0];   // (2, 2048, 2048)
    const float* Wqkv     = (const float*)d_in[1];   // (2048, 3072)
    const float* Wo       = (const float*)d_in[2];   // (2048, 2048)
    const int*   startpos = (const int*)d_in[3];     // scalar
    float* out = (float*)d_out;                      // (2, 2048, 2048)

    __half *qkvh, *yh, *xh, *wqT, *woT;
    cudaGetSymbolAddress((void**)&qkvh, g_qkvh);
    cudaGetSymbolAddress((void**)&yh, g_yh);
    cudaGetSymbolAddress((void**)&xh, g_xh);
    cudaGetSymbolAddress((void**)&wqT, g_wqT);
    cudaGetSymbolAddress((void**)&woT, g_woT);

    cudaFuncSetAttribute((void*)gemm_h<true, true>,   cudaFuncAttributeMaxDynamicSharedMemorySize, GEMM_SMEM);
    cudaFuncSetAttribute((void*)gemm_h<false, false>, cudaFuncAttributeMaxDynamicSharedMemorySize, GEMM_SMEM);
    cudaFuncSetAttribute((void*)flash_h, cudaFuncAttributeMaxDynamicSharedMemorySize, FLASH_SMEM);

    // 0) pre-pass: (x conv + rope table) and (both weight transposes)
    prep_misc_kernel<<<8704, 256>>>(x, (__half2*)xh, startpos);
    transpose_h_kernel<<<dim3(QKV_DIM / 32, D_MODEL / 64, 2), dim3(32, 8)>>>(Wqkv, Wo);

    // 1) qkv = x @ Wqkv with fused RoPE (fp16 out)
    dim3 g1(QKV_DIM / 128, ROWS / 128);
    gemm_h<true, true><<<g1, 128, GEMM_SMEM>>>(xh, wqT, qkvh, ROWS, QKV_DIM, D_MODEL);

    // 2) flash attention -> yh (fp16)
    dim3 g3(N_HEADS * B_, T_ / 64, 1);
    flash_h<<<g3, 128, FLASH_SMEM>>>(qkvh, yh);

    // 3) out = y @ Wo  (fp32 out)
    dim3 g4(D_MODEL / 128, ROWS / 128);
    gemm_h<false, false><<<g4, 128, GEMM_SMEM>>>(yh, woT, out, ROWS, D_MODEL, D_MODEL);
}